// round 1
// baseline (speedup 1.0000x reference)
#include <cuda_runtime.h>
#include <cuda_bf16.h>
#include <cstdint>

// ---------------------------------------------------------------------------
// CliffordLinear as one dense GEMM:
//   out[b, o*8+l] = sum_{i,k} X[b, i*8+k] * Wt[(i*8+k), (o*8+l)] + bias[o*8+l]
//   Wt[(i,k),(o,l)] = cayley[k^l, k, l] * W[o, i, k^l]
// Shapes: M=8192 (batch), N=2048 (=256 out-ch * 8 blades), K=2048 (=256 in-ch * 8 blades)
// ---------------------------------------------------------------------------

#define M_DIM 8192
#define N_DIM 2048
#define K_DIM 2048
#define N_BLADES 8

// 16 MB scratch for the transformed weight matrix (row-major [K, N]).
// __device__ global (static module allocation) — allowed; no cudaMalloc.
__device__ float g_Wt[K_DIM * N_DIM];

// ---------------------------------------------------------------------------
// Prologue: build Wt[(i*8+k), (o*8+l)] = cayley[j*64 + k*8 + l] * W[o,i,j], j=k^l
// ---------------------------------------------------------------------------
__global__ void __launch_bounds__(1024) build_wt_kernel(const float* __restrict__ weight,
                                                        const float* __restrict__ cayley) {
    int t = blockIdx.x * blockDim.x + threadIdx.x;   // 0 .. 4M-1
    if (t >= K_DIM * N_DIM) return;
    int row = t >> 11;          // i*8 + k   (K index)
    int col = t & 2047;         // o*8 + l   (N index)
    int i = row >> 3, k = row & 7;
    int o = col >> 3, l = col & 7;
    int j = k ^ l;
    float c = cayley[(j * 8 + k) * 8 + l];           // = sign(j,k), nonzero since j^k==l
    g_Wt[t] = c * weight[(o * 256 + i) * 8 + j];
}

// ---------------------------------------------------------------------------
// Main GEMM: C = X * Wt + bias.  BM=128, BN=128, BK=16, 256 threads, 8x8/thread
// ---------------------------------------------------------------------------
#define BM 128
#define BN 128
#define BK 16

__global__ void __launch_bounds__(256) clifford_gemm_kernel(const float* __restrict__ A,
                                                            const float* __restrict__ bias,
                                                            float* __restrict__ C) {
    __shared__ float As[BK][BM];       // A tile, transposed to [k][m]
    __shared__ float Bs[BK][BN];       // Wt tile [k][n]

    const int tid = threadIdx.x;
    const int tx = tid & 15;           // 0..15 along N
    const int ty = tid >> 4;           // 0..15 along M

    const int block_m = blockIdx.y * BM;
    const int block_n = blockIdx.x * BN;

    const float* Aptr = A + (size_t)block_m * K_DIM;

    float acc[8][8];
#pragma unroll
    for (int u = 0; u < 8; u++)
#pragma unroll
        for (int v = 0; v < 8; v++) acc[u][v] = 0.0f;

    for (int k0 = 0; k0 < K_DIM; k0 += BK) {
        // ---- load A tile: 128 rows x 16 cols = 512 float4, 2 per thread ----
#pragma unroll
        for (int r = 0; r < 2; r++) {
            int f = tid + r * 256;          // 0..511
            int m  = f >> 2;                // 0..127
            int kv = (f & 3) * 4;           // 0,4,8,12
            float4 v = *reinterpret_cast<const float4*>(Aptr + (size_t)m * K_DIM + k0 + kv);
            As[kv + 0][m] = v.x;
            As[kv + 1][m] = v.y;
            As[kv + 2][m] = v.z;
            As[kv + 3][m] = v.w;
        }
        // ---- load B tile: 16 rows x 128 cols = 512 float4, 2 per thread ----
#pragma unroll
        for (int r = 0; r < 2; r++) {
            int f = tid + r * 256;
            int kk = f >> 5;                // 0..15
            int nv = (f & 31) * 4;          // 0..124
            *reinterpret_cast<float4*>(&Bs[kk][nv]) =
                *reinterpret_cast<const float4*>(g_Wt + (size_t)(k0 + kk) * N_DIM + block_n + nv);
        }
        __syncthreads();

        // ---- compute ----
#pragma unroll
        for (int kk = 0; kk < BK; kk++) {
            float a[8], b[8];
            float4 a0 = *reinterpret_cast<const float4*>(&As[kk][ty * 8]);
            float4 a1 = *reinterpret_cast<const float4*>(&As[kk][ty * 8 + 4]);
            float4 b0 = *reinterpret_cast<const float4*>(&Bs[kk][tx * 8]);
            float4 b1 = *reinterpret_cast<const float4*>(&Bs[kk][tx * 8 + 4]);
            a[0]=a0.x; a[1]=a0.y; a[2]=a0.z; a[3]=a0.w; a[4]=a1.x; a[5]=a1.y; a[6]=a1.z; a[7]=a1.w;
            b[0]=b0.x; b[1]=b0.y; b[2]=b0.z; b[3]=b0.w; b[4]=b1.x; b[5]=b1.y; b[6]=b1.z; b[7]=b1.w;
#pragma unroll
            for (int u = 0; u < 8; u++)
#pragma unroll
                for (int v = 0; v < 8; v++) acc[u][v] = fmaf(a[u], b[v], acc[u][v]);
        }
        __syncthreads();
    }

    // ---- epilogue: add bias, store ----
#pragma unroll
    for (int u = 0; u < 8; u++) {
        int m = block_m + ty * 8 + u;
#pragma unroll
        for (int v = 0; v < 8; v += 4) {
            int n = block_n + tx * 8 + v;
            float4 bv = *reinterpret_cast<const float4*>(bias + n);
            float4 o;
            o.x = acc[u][v + 0] + bv.x;
            o.y = acc[u][v + 1] + bv.y;
            o.z = acc[u][v + 2] + bv.z;
            o.w = acc[u][v + 3] + bv.w;
            *reinterpret_cast<float4*>(C + (size_t)m * N_DIM + n) = o;
        }
    }
}

// ---------------------------------------------------------------------------
// Launch: inputs per metadata order: x, weight, bias, cayley
// ---------------------------------------------------------------------------
extern "C" void kernel_launch(void* const* d_in, const int* in_sizes, int n_in,
                              void* d_out, int out_size) {
    const float* x      = (const float*)d_in[0];   // [8192, 256, 8]
    const float* weight = (const float*)d_in[1];   // [256, 256, 8]
    const float* bias   = (const float*)d_in[2];   // [256, 8]
    const float* cayley = (const float*)d_in[3];   // [8, 8, 8]
    float* out = (float*)d_out;                    // [8192, 256, 8]

    (void)in_sizes; (void)n_in; (void)out_size;

    // 1) transform weights into dense [K=2048, N=2048] matrix
    int total = K_DIM * N_DIM;
    build_wt_kernel<<<(total + 1023) / 1024, 1024>>>(weight, cayley);

    // 2) GEMM + bias
    dim3 grid(N_DIM / BN, M_DIM / BM);   // (16, 64)
    clifford_gemm_kernel<<<grid, 256>>>(x, bias, out);
}

// round 3
// speedup vs baseline: 3.2004x; 3.2004x over previous
#include <cuda_runtime.h>
#include <cstdint>

// ---------------------------------------------------------------------------
// CliffordLinear as one dense GEMM via mma.sync tf32 (tcgen05 unavailable:
// harness PTX target is sm_103 without the 'a' feature suffix).
//   out[b, o*8+l] = sum_{i,k} X[b, i*8+k] * WtT[(o*8+l), (i*8+k)] + bias
//   WtT[(o,l),(i,k)] = cayley[k^l, k, l] * W[o, i, k^l]   (tf32-rounded)
// M=8192, N=2048, K=2048. A = x row-major [M,K]; B = WtT row-major [N,K].
// ---------------------------------------------------------------------------

#define M_DIM 8192
#define N_DIM 2048
#define K_DIM 2048

__device__ float g_WtT[N_DIM * K_DIM];   // 16 MB static scratch (allowed)

__device__ __forceinline__ float tf32_rn(float x) {
    uint32_t r;
    asm("cvt.rna.tf32.f32 %0, %1;" : "=r"(r) : "f"(x));
    return __uint_as_float(r);
}

// ---------------------------------------------------------------------------
// Prologue: WtT[n][kk] = round_tf32( cayley[j,k,l] * W[o,i,j] ), j=k^l
// ---------------------------------------------------------------------------
__global__ void __launch_bounds__(1024) build_wt_kernel(const float* __restrict__ weight,
                                                        const float* __restrict__ cayley) {
    int t = blockIdx.x * blockDim.x + threadIdx.x;
    if (t >= N_DIM * K_DIM) return;
    int n  = t >> 11;        // o*8 + l
    int kk = t & 2047;       // i*8 + k
    int o = n >> 3,  l = n & 7;
    int i = kk >> 3, k = kk & 7;
    int j = k ^ l;
    g_WtT[t] = tf32_rn(cayley[(j * 8 + k) * 8 + l] * weight[(o * 256 + i) * 8 + j]);
}

// ---------------------------------------------------------------------------
// GEMM: BM=128, BN=128, BK=32, 3 stages, 256 threads (2x4 warps, 64x32/warp)
// smem per stage: A 128x36 floats + B 128x36 floats (pad 4 -> conflict-free)
// ---------------------------------------------------------------------------
#define BM 128
#define BN 128
#define BK 32
#define BKP 36                       /* padded row stride in floats */
#define TILE_FLOATS (128 * BKP)      /* 4608 */
#define STAGE_BYTES (2 * TILE_FLOATS * 4)   /* 36864 */
#define NSTAGES 3
#define SMEM_TOTAL (NSTAGES * STAGE_BYTES)  /* 110592 */
#define NUM_ITERS (K_DIM / BK)       /* 64 */

__device__ __forceinline__ void mma_tf32(float& c0, float& c1, float& c2, float& c3,
                                         uint32_t a0, uint32_t a1, uint32_t a2, uint32_t a3,
                                         uint32_t b0, uint32_t b1) {
    asm volatile(
        "mma.sync.aligned.m16n8k8.row.col.f32.tf32.tf32.f32 "
        "{%0,%1,%2,%3}, {%4,%5,%6,%7}, {%8,%9}, {%0,%1,%2,%3};"
        : "+f"(c0), "+f"(c1), "+f"(c2), "+f"(c3)
        : "r"(a0), "r"(a1), "r"(a2), "r"(a3), "r"(b0), "r"(b1));
}

__global__ void __launch_bounds__(256, 1) clifford_mma_kernel(
    const float* __restrict__ A, const float* __restrict__ bias, float* __restrict__ C)
{
    extern __shared__ float smem[];
    const int tid  = threadIdx.x;
    const int wid  = tid >> 5;
    const int lane = tid & 31;
    const int wm = wid & 1;          // warp row (2 along M)
    const int wn = wid >> 1;         // warp col (4 along N)
    const int lr = lane >> 2;        // 0..7
    const int lc = lane & 3;         // 0..3

    const int block_m = blockIdx.y * BM;
    const int block_n = blockIdx.x * BN;

    const float* Abase = A     + (size_t)block_m * K_DIM;
    const float* Bbase = g_WtT + (size_t)block_n * K_DIM;

    uint32_t smem_u;
    asm("{ .reg .u64 t; cvta.to.shared.u64 t, %1; cvt.u32.u64 %0, t; }"
        : "=r"(smem_u) : "l"(smem));

    // Stage loader: 128 rows x 8 k-chunks (16B) per matrix; 1024 chunks each,
    // 4 per thread per matrix. Row stride 144B (16B-aligned), coalesced gmem.
#define LOAD_STAGE(s, k0) do {                                                      \
        uint32_t soff_ = smem_u + (uint32_t)(s) * STAGE_BYTES;                      \
        _Pragma("unroll")                                                           \
        for (int t_ = 0; t_ < 4; t_++) {                                            \
            int c_ = t_ * 256 + tid;                                                \
            int row_ = c_ >> 3, kq_ = c_ & 7;                                       \
            uint32_t so_ = soff_ + (uint32_t)(row_ * (BKP * 4) + kq_ * 16);         \
            const float* ga_ = Abase + (size_t)row_ * K_DIM + (k0) + kq_ * 4;       \
            asm volatile("cp.async.cg.shared.global [%0], [%1], 16;"                \
                         :: "r"(so_), "l"(ga_));                                    \
            const float* gb_ = Bbase + (size_t)row_ * K_DIM + (k0) + kq_ * 4;       \
            asm volatile("cp.async.cg.shared.global [%0], [%1], 16;"                \
                         :: "r"(so_ + TILE_FLOATS * 4), "l"(gb_));                  \
        }                                                                           \
    } while (0)

    float acc[4][4][4];
#pragma unroll
    for (int mi = 0; mi < 4; mi++)
#pragma unroll
        for (int ni = 0; ni < 4; ni++)
#pragma unroll
            for (int q = 0; q < 4; q++) acc[mi][ni][q] = 0.0f;

    // prologue: stages 0,1
    LOAD_STAGE(0, 0);
    asm volatile("cp.async.commit_group;" ::: "memory");
    LOAD_STAGE(1, BK);
    asm volatile("cp.async.commit_group;" ::: "memory");

    for (int it = 0; it < NUM_ITERS; ++it) {
        asm volatile("cp.async.wait_group 1;" ::: "memory");
        __syncthreads();

        if (it + 2 < NUM_ITERS) LOAD_STAGE((it + 2) % NSTAGES, (it + 2) * BK);
        asm volatile("cp.async.commit_group;" ::: "memory");

        const float* As = smem + (size_t)(it % NSTAGES) * (2 * TILE_FLOATS);
        const float* Bs = As + TILE_FLOATS;

#pragma unroll
        for (int ks = 0; ks < 4; ks++) {
            const int k0 = ks * 8;
            uint32_t af[4][4], bf[4][2];
#pragma unroll
            for (int mi = 0; mi < 4; mi++) {
                int r = wm * 64 + mi * 16 + lr;
                af[mi][0] = __float_as_uint(tf32_rn(As[(r    ) * BKP + k0 + lc    ]));
                af[mi][1] = __float_as_uint(tf32_rn(As[(r + 8) * BKP + k0 + lc    ]));
                af[mi][2] = __float_as_uint(tf32_rn(As[(r    ) * BKP + k0 + lc + 4]));
                af[mi][3] = __float_as_uint(tf32_rn(As[(r + 8) * BKP + k0 + lc + 4]));
            }
#pragma unroll
            for (int ni = 0; ni < 4; ni++) {
                int n = wn * 32 + ni * 8 + lr;          // B already tf32-rounded
                bf[ni][0] = __float_as_uint(Bs[n * BKP + k0 + lc    ]);
                bf[ni][1] = __float_as_uint(Bs[n * BKP + k0 + lc + 4]);
            }
#pragma unroll
            for (int mi = 0; mi < 4; mi++)
#pragma unroll
                for (int ni = 0; ni < 4; ni++)
                    mma_tf32(acc[mi][ni][0], acc[mi][ni][1], acc[mi][ni][2], acc[mi][ni][3],
                             af[mi][0], af[mi][1], af[mi][2], af[mi][3],
                             bf[ni][0], bf[ni][1]);
        }
    }

    // ---- epilogue: add bias, store ----
#pragma unroll
    for (int mi = 0; mi < 4; mi++) {
        int row0 = block_m + wm * 64 + mi * 16 + lr;
#pragma unroll
        for (int ni = 0; ni < 4; ni++) {
            int col = block_n + wn * 32 + ni * 8 + 2 * lc;
            float2 bv = *reinterpret_cast<const float2*>(bias + col);
            float2 o0, o1;
            o0.x = acc[mi][ni][0] + bv.x;
            o0.y = acc[mi][ni][1] + bv.y;
            o1.x = acc[mi][ni][2] + bv.x;
            o1.y = acc[mi][ni][3] + bv.y;
            *reinterpret_cast<float2*>(C + (size_t)row0 * N_DIM + col) = o0;
            *reinterpret_cast<float2*>(C + (size_t)(row0 + 8) * N_DIM + col) = o1;
        }
    }
}

// ---------------------------------------------------------------------------
// Launch.  Inputs: x, weight, bias, cayley (metadata order).
// ---------------------------------------------------------------------------
extern "C" void kernel_launch(void* const* d_in, const int* in_sizes, int n_in,
                              void* d_out, int out_size) {
    const float* x      = (const float*)d_in[0];   // [8192, 256, 8]
    const float* weight = (const float*)d_in[1];   // [256, 256, 8]
    const float* bias   = (const float*)d_in[2];   // [256, 8]
    const float* cayley = (const float*)d_in[3];   // [8, 8, 8]
    float* out = (float*)d_out;                    // [8192, 256, 8]
    (void)in_sizes; (void)n_in; (void)out_size;

    int total = N_DIM * K_DIM;
    build_wt_kernel<<<(total + 1023) / 1024, 1024>>>(weight, cayley);

    cudaFuncSetAttribute(clifford_mma_kernel,
                         cudaFuncAttributeMaxDynamicSharedMemorySize, SMEM_TOTAL);
    dim3 grid(N_DIM / BN, M_DIM / BM);   // (16, 64)
    clifford_mma_kernel<<<grid, 256, SMEM_TOTAL>>>(x, bias, out);
}